// round 1
// baseline (speedup 1.0000x reference)
#include <cuda_runtime.h>
#include <math.h>

#define S_LEN 2048
#define B_SZ  64
#define E_SZ  256
#define H_SZ  256

// Scratch for x_proj: [S, B, H] fp32 = 134 MB (static device alloc is allowed)
__device__ float g_xproj[(size_t)S_LEN * B_SZ * H_SZ];

// ---------------------------------------------------------------------------
// Kernel 1: x_proj[m][j] = sum_e sent[m][e] * W_ih[e][j] + b[j],  m = s*B + b
// CTA: 256 threads, 8 rows of the flattened [S*B, E] input.
// Thread (ks = t>>6, jg = t&63): k-split 4-way, owns 4 contiguous columns.
// ---------------------------------------------------------------------------
__global__ __launch_bounds__(256) void xproj_kernel(
    const float* __restrict__ sent,   // [S*B, 256]
    const float* __restrict__ Wih,    // [256, 256] row-major (e, h)
    const float* __restrict__ bias)   // [256]
{
    __shared__ float xs[8][256];        // 8 input rows
    __shared__ float part[4][8][256];   // k-split partials (32 KB)

    const int t  = threadIdx.x;
    const int m0 = blockIdx.x * 8;

    // Load 8 input rows to SMEM (float4, coalesced)
    {
        const float4* srow = (const float4*)(sent + (size_t)m0 * 256);
        float4* xs4 = (float4*)&xs[0][0];
        #pragma unroll
        for (int i = 0; i < 2; i++)
            xs4[t + i * 256] = srow[t + i * 256];
    }
    __syncthreads();

    const int jg = t & 63;
    const int ks = t >> 6;
    const float4* W4 = (const float4*)Wih;

    float4 acc[8];
    #pragma unroll
    for (int r = 0; r < 8; r++) acc[r] = make_float4(0.f, 0.f, 0.f, 0.f);

    #pragma unroll 8
    for (int i = 0; i < 64; i++) {
        const int k = ks * 64 + i;
        const float4 w = W4[k * 64 + jg];
        #pragma unroll
        for (int r = 0; r < 8; r++) {
            const float xv = xs[r][k];
            acc[r].x += xv * w.x;
            acc[r].y += xv * w.y;
            acc[r].z += xv * w.z;
            acc[r].w += xv * w.w;
        }
    }

    #pragma unroll
    for (int r = 0; r < 8; r++)
        *(float4*)&part[ks][r][4 * jg] = acc[r];
    __syncthreads();

    const float bj = bias[t];
    #pragma unroll
    for (int r = 0; r < 8; r++) {
        const float v = part[0][r][t] + part[1][r][t] +
                        part[2][r][t] + part[3][r][t] + bj;
        g_xproj[(size_t)(m0 + r) * 256 + t] = v;
    }
}

// ---------------------------------------------------------------------------
// Kernel 2: the scan. One CTA per 2 batch rows (32 CTAs, fully independent
// recurrences -> zero inter-CTA sync). W_hh streamed from L2 each step.
// Thread (ks = t>>6, jg = t&63): 4-way k-split, 4 contiguous output columns,
// both batch rows accumulated per W element (2x register reuse).
// ---------------------------------------------------------------------------
__global__ __launch_bounds__(256) void scan_kernel(
    const float* __restrict__ Whh,    // [256, 256] row-major (k, j)
    const float* __restrict__ h0,     // [64, 256]
    float* __restrict__ out)          // [64, 256]
{
    __shared__ float2 hbuf[256];        // h[k] interleaved for rows (b0, b0+1)
    __shared__ float  part[4][2][256];  // k-split partials (8 KB)

    const int t  = threadIdx.x;
    const int b0 = blockIdx.x * 2;

    hbuf[t] = make_float2(h0[(size_t)b0 * 256 + t],
                          h0[(size_t)(b0 + 1) * 256 + t]);
    __syncthreads();

    const int jg = t & 63;
    const int ks = t >> 6;
    const float4* W4 = (const float4*)Whh;

    for (int s = 0; s < S_LEN; s++) {
        // Prefetch this step's x_proj (consumed ~2000 cycles later)
        const float* xps = g_xproj + ((size_t)s * B_SZ + b0) * 256;
        const float xv0 = xps[t];
        const float xv1 = xps[256 + t];

        float4 a0 = make_float4(0.f, 0.f, 0.f, 0.f);
        float4 a1 = make_float4(0.f, 0.f, 0.f, 0.f);

        #pragma unroll 16
        for (int i = 0; i < 64; i++) {
            const int k = ks * 64 + i;
            const float4 w = W4[k * 64 + jg];
            const float2 hv = hbuf[k];
            a0.x += hv.x * w.x;
            a0.y += hv.x * w.y;
            a0.z += hv.x * w.z;
            a0.w += hv.x * w.w;
            a1.x += hv.y * w.x;
            a1.y += hv.y * w.y;
            a1.z += hv.y * w.z;
            a1.w += hv.y * w.w;
        }

        *(float4*)&part[ks][0][4 * jg] = a0;
        *(float4*)&part[ks][1][4 * jg] = a1;
        __syncthreads();   // (A) partials visible; all hbuf reads done

        const float v0 = part[0][0][t] + part[1][0][t] +
                         part[2][0][t] + part[3][0][t] + xv0;
        const float v1 = part[0][1][t] + part[1][1][t] +
                         part[2][1][t] + part[3][1][t] + xv1;

        hbuf[t] = make_float2(tanhf(v0), tanhf(v1));
        __syncthreads();   // (B) new h visible before next step's reads
    }

    const float2 hf = hbuf[t];
    out[(size_t)b0 * 256 + t]       = hf.x;
    out[(size_t)(b0 + 1) * 256 + t] = hf.y;
}

// ---------------------------------------------------------------------------
// Launch: inputs in metadata order: sentence, h0, W_ih, W_hh, b
// ---------------------------------------------------------------------------
extern "C" void kernel_launch(void* const* d_in, const int* in_sizes, int n_in,
                              void* d_out, int out_size)
{
    const float* sentence = (const float*)d_in[0]; // [2048, 64, 256]
    const float* h0       = (const float*)d_in[1]; // [64, 256]
    const float* W_ih     = (const float*)d_in[2]; // [256, 256]
    const float* W_hh     = (const float*)d_in[3]; // [256, 256]
    const float* bias     = (const float*)d_in[4]; // [256]
    float* out = (float*)d_out;                    // [64, 256]

    (void)in_sizes; (void)n_in; (void)out_size;

    // x_proj for all (s, b) rows: 131072 rows / 8 per CTA
    xproj_kernel<<<(S_LEN * B_SZ) / 8, 256>>>(sentence, W_ih, bias);

    // Sequential scan: 32 independent CTAs (2 batch rows each)
    scan_kernel<<<B_SZ / 2, 256>>>(W_hh, h0, out);
}

// round 2
// speedup vs baseline: 5.0519x; 5.0519x over previous
#include <cuda_runtime.h>
#include <math.h>

#define S_LEN 2048
#define B_SZ  64
#define E_SZ  256
#define H_SZ  256

// Scratch for x_proj: [S, B, H] fp32 = 134 MB
__device__ float g_xproj[(size_t)S_LEN * B_SZ * H_SZ];

typedef unsigned long long ull;

// ---- packed f32x2 helpers (Blackwell sm_103a) -------------------------------
__device__ __forceinline__ ull fma2(ull a, ull b, ull c) {
    ull d;
    asm("fma.rn.f32x2 %0, %1, %2, %3;" : "=l"(d) : "l"(a), "l"(b), "l"(c));
    return d;
}
__device__ __forceinline__ ull add2(ull a, ull b) {
    ull d;
    asm("add.rn.f32x2 %0, %1, %2;" : "=l"(d) : "l"(a), "l"(b));
    return d;
}
__device__ __forceinline__ ull pack2(float lo, float hi) {
    ull d;
    asm("mov.b64 %0, {%1, %2};" : "=l"(d) : "f"(lo), "f"(hi));
    return d;
}
__device__ __forceinline__ void unpack2(ull v, float& lo, float& hi) {
    asm("mov.b64 {%0, %1}, %2;" : "=f"(lo), "=f"(hi) : "l"(v));
}

// ---------------------------------------------------------------------------
// Kernel 1: x_proj = sentence @ W_ih + b   (unchanged from R1 — works, ~0.4ms)
// ---------------------------------------------------------------------------
__global__ __launch_bounds__(256) void xproj_kernel(
    const float* __restrict__ sent,
    const float* __restrict__ Wih,
    const float* __restrict__ bias)
{
    __shared__ float xs[8][256];
    __shared__ float part[4][8][256];

    const int t  = threadIdx.x;
    const int m0 = blockIdx.x * 8;

    {
        const float4* srow = (const float4*)(sent + (size_t)m0 * 256);
        float4* xs4 = (float4*)&xs[0][0];
        #pragma unroll
        for (int i = 0; i < 2; i++)
            xs4[t + i * 256] = srow[t + i * 256];
    }
    __syncthreads();

    const int jg = t & 63;
    const int ks = t >> 6;
    const float4* W4 = (const float4*)Wih;

    float4 acc[8];
    #pragma unroll
    for (int r = 0; r < 8; r++) acc[r] = make_float4(0.f, 0.f, 0.f, 0.f);

    #pragma unroll 8
    for (int i = 0; i < 64; i++) {
        const int k = ks * 64 + i;
        const float4 w = W4[k * 64 + jg];
        #pragma unroll
        for (int r = 0; r < 8; r++) {
            const float xv = xs[r][k];
            acc[r].x += xv * w.x;
            acc[r].y += xv * w.y;
            acc[r].z += xv * w.z;
            acc[r].w += xv * w.w;
        }
    }

    #pragma unroll
    for (int r = 0; r < 8; r++)
        *(float4*)&part[ks][r][4 * jg] = acc[r];
    __syncthreads();

    const float bj = bias[t];
    #pragma unroll
    for (int r = 0; r < 8; r++) {
        const float v = part[0][r][t] + part[1][r][t] +
                        part[2][r][t] + part[3][r][t] + bj;
        g_xproj[(size_t)(m0 + r) * 256 + t] = v;
    }
}

// ---------------------------------------------------------------------------
// Kernel 2: the scan. 64 CTAs, one batch row each (independent recurrences).
// 512 threads: ks = t>>6 (8-way k-split, 32 k's), jq = t&63 (4 columns).
// W_hh resident: per thread, k-range first 20 k's in REGISTERS (40 f32x2 =
// 80 regs), last 12 k's in SMEM (96 KB). Zero gmem W traffic in steady state.
// h kept in SMEM pre-replicated as (h,h) f32x2 pairs -> no packing in loop.
// Math via fma.rn.f32x2 (FFMA2): 2 FMAs/instr.
// ---------------------------------------------------------------------------
#define K_REG  20
#define K_SMEM 12

__global__ __launch_bounds__(512, 1) void scan_kernel(
    const float* __restrict__ Whh,    // [256,256] row-major (k, j)
    const float* __restrict__ h0,     // [64,256]
    float* __restrict__ out)          // [64,256]
{
    extern __shared__ ull smem[];
    // layout: sW [8][12][64] ulonglong2  (96 KB)
    //         part [8][128] ull          (8 KB)
    //         hbuf [256] ull             (2 KB)
    ulonglong2* sW   = (ulonglong2*)smem;                       // 8*12*64 entries
    ull*        part = (ull*)(smem + 8 * 12 * 64 * 2);          // 8*128
    ull*        hbuf = part + 8 * 128;                          // 256

    const int t  = threadIdx.x;
    const int b  = blockIdx.x;
    const int ks = t >> 6;        // 0..7
    const int jq = t & 63;        // 4 columns: 4jq .. 4jq+3
    const int kbase = ks * 32;

    // ---- one-time: load register-resident W slice (20 k's x 4 cols) ----
    ull wr[2 * K_REG];
    #pragma unroll
    for (int i = 0; i < K_REG; i++) {
        const int k = kbase + i;
        const ulonglong2 wv = *(const ulonglong2*)&Whh[k * 256 + 4 * jq];
        wr[2 * i]     = wv.x;   // cols (4jq, 4jq+1)
        wr[2 * i + 1] = wv.y;   // cols (4jq+2, 4jq+3)
    }

    // ---- one-time: fill SMEM W slice (12 k's per ks-group) ----
    for (int idx = t; idx < 8 * K_SMEM * 64; idx += 512) {
        const int fjq = idx & 63;
        const int fm  = (idx >> 6) % K_SMEM;
        const int fks = idx / (K_SMEM * 64);
        const int k   = fks * 32 + K_REG + fm;
        sW[(fks * K_SMEM + fm) * 64 + fjq] =
            *(const ulonglong2*)&Whh[k * 256 + 4 * fjq];
    }

    // ---- init h (replicated pairs) ----
    if (t < 256) {
        const float h = h0[(size_t)b * 256 + t];
        hbuf[t] = pack2(h, h);
    }
    __syncthreads();

    // x_proj prefetch state (threads t<128 own column-pair t)
    ull xcur = 0, xnext = 0;
    if (t < 128) {
        xcur = *(const ull*)&g_xproj[((size_t)0 * B_SZ + b) * 256 + 2 * t];
    }

    const ull* hb = hbuf + kbase;

    for (int s = 0; s < S_LEN; s++) {
        // prefetch next step's x (lands during this step's FMA phase)
        if (t < 128) {
            const int sn = (s + 1 < S_LEN) ? s + 1 : s;
            xnext = *(const ull*)&g_xproj[((size_t)sn * B_SZ + b) * 256 + 2 * t];
        }

        ull a01 = 0, a23 = 0;   // packed (0.0f,0.0f)

        // register half: k = kbase + 0 .. kbase + 19
        #pragma unroll
        for (int p = 0; p < K_REG / 2; p++) {
            const ulonglong2 hv = *(const ulonglong2*)(hb + 2 * p);
            a01 = fma2(wr[4 * p + 0], hv.x, a01);
            a23 = fma2(wr[4 * p + 1], hv.x, a23);
            a01 = fma2(wr[4 * p + 2], hv.y, a01);
            a23 = fma2(wr[4 * p + 3], hv.y, a23);
        }
        // smem half: k = kbase + 20 .. kbase + 31
        #pragma unroll
        for (int m = 0; m < K_SMEM; m += 2) {
            const ulonglong2 hv = *(const ulonglong2*)(hb + K_REG + m);
            const ulonglong2 w0 = sW[(ks * K_SMEM + m) * 64 + jq];
            const ulonglong2 w1 = sW[(ks * K_SMEM + m + 1) * 64 + jq];
            a01 = fma2(w0.x, hv.x, a01);
            a23 = fma2(w0.y, hv.x, a23);
            a01 = fma2(w1.x, hv.y, a01);
            a23 = fma2(w1.y, hv.y, a23);
        }

        // partials: col-pair index cp = 2*jq (+0/+1)
        part[ks * 128 + 2 * jq]     = a01;
        part[ks * 128 + 2 * jq + 1] = a23;
        __syncthreads();

        // reduce 8 k-groups, add x, tanh, write replicated h
        if (t < 128) {
            ull v = add2(add2(part[0 * 128 + t], part[1 * 128 + t]),
                         add2(part[2 * 128 + t], part[3 * 128 + t]));
            ull w = add2(add2(part[4 * 128 + t], part[5 * 128 + t]),
                         add2(part[6 * 128 + t], part[7 * 128 + t]));
            v = add2(add2(v, w), xcur);
            float vx, vy;
            unpack2(v, vx, vy);
            const float tx = tanhf(vx);
            const float ty = tanhf(vy);
            hbuf[2 * t]     = pack2(tx, tx);
            hbuf[2 * t + 1] = pack2(ty, ty);
            xcur = xnext;
        }
        __syncthreads();
    }

    if (t < 128) {
        float vx, vy;
        unpack2(hbuf[2 * t], vx, vy);   // both halves equal
        float wx, wy;
        unpack2(hbuf[2 * t + 1], wx, wy);
        out[(size_t)b * 256 + 2 * t]     = vx;
        out[(size_t)b * 256 + 2 * t + 1] = wx;
    }
}

// ---------------------------------------------------------------------------
extern "C" void kernel_launch(void* const* d_in, const int* in_sizes, int n_in,
                              void* d_out, int out_size)
{
    const float* sentence = (const float*)d_in[0];
    const float* h0       = (const float*)d_in[1];
    const float* W_ih     = (const float*)d_in[2];
    const float* W_hh     = (const float*)d_in[3];
    const float* bias     = (const float*)d_in[4];
    float* out = (float*)d_out;

    (void)in_sizes; (void)n_in; (void)out_size;

    xproj_kernel<<<(S_LEN * B_SZ) / 8, 256>>>(sentence, W_ih, bias);

    const int smem_bytes = (8 * K_SMEM * 64) * 16 + (8 * 128) * 8 + 256 * 8;
    static bool attr_set = false;
    if (!attr_set) {
        cudaFuncSetAttribute(scan_kernel,
                             cudaFuncAttributeMaxDynamicSharedMemorySize,
                             smem_bytes);
        attr_set = true;
    }
    scan_kernel<<<B_SZ, 512, smem_bytes>>>(W_hh, h0, out);
}

// round 3
// speedup vs baseline: 5.0547x; 1.0006x over previous
#include <cuda_runtime.h>
#include <math.h>

#define S_LEN 2048
#define B_SZ  64
#define E_SZ  256
#define H_SZ  256

// Scratch for x_proj: [S, B, H] fp32 = 134 MB
__device__ float g_xproj[(size_t)S_LEN * B_SZ * H_SZ];

typedef unsigned long long ull;

// ---- packed f32x2 helpers (Blackwell sm_103a) -------------------------------
__device__ __forceinline__ ull fma2(ull a, ull b, ull c) {
    ull d;
    asm("fma.rn.f32x2 %0, %1, %2, %3;" : "=l"(d) : "l"(a), "l"(b), "l"(c));
    return d;
}
__device__ __forceinline__ ull add2(ull a, ull b) {
    ull d;
    asm("add.rn.f32x2 %0, %1, %2;" : "=l"(d) : "l"(a), "l"(b));
    return d;
}
__device__ __forceinline__ ull pack2(float lo, float hi) {
    ull d;
    asm("mov.b64 %0, {%1, %2};" : "=l"(d) : "f"(lo), "f"(hi));
    return d;
}
__device__ __forceinline__ void unpack2(ull v, float& lo, float& hi) {
    asm("mov.b64 {%0, %1}, %2;" : "=f"(lo), "=f"(hi) : "l"(v));
}

// ---------------------------------------------------------------------------
// Kernel 1: x_proj = sentence @ W_ih + b   (unchanged from R1 — works, ~0.4ms)
// ---------------------------------------------------------------------------
__global__ __launch_bounds__(256) void xproj_kernel(
    const float* __restrict__ sent,
    const float* __restrict__ Wih,
    const float* __restrict__ bias)
{
    __shared__ float xs[8][256];
    __shared__ float part[4][8][256];

    const int t  = threadIdx.x;
    const int m0 = blockIdx.x * 8;

    {
        const float4* srow = (const float4*)(sent + (size_t)m0 * 256);
        float4* xs4 = (float4*)&xs[0][0];
        #pragma unroll
        for (int i = 0; i < 2; i++)
            xs4[t + i * 256] = srow[t + i * 256];
    }
    __syncthreads();

    const int jg = t & 63;
    const int ks = t >> 6;
    const float4* W4 = (const float4*)Wih;

    float4 acc[8];
    #pragma unroll
    for (int r = 0; r < 8; r++) acc[r] = make_float4(0.f, 0.f, 0.f, 0.f);

    #pragma unroll 8
    for (int i = 0; i < 64; i++) {
        const int k = ks * 64 + i;
        const float4 w = W4[k * 64 + jg];
        #pragma unroll
        for (int r = 0; r < 8; r++) {
            const float xv = xs[r][k];
            acc[r].x += xv * w.x;
            acc[r].y += xv * w.y;
            acc[r].z += xv * w.z;
            acc[r].w += xv * w.w;
        }
    }

    #pragma unroll
    for (int r = 0; r < 8; r++)
        *(float4*)&part[ks][r][4 * jg] = acc[r];
    __syncthreads();

    const float bj = bias[t];
    #pragma unroll
    for (int r = 0; r < 8; r++) {
        const float v = part[0][r][t] + part[1][r][t] +
                        part[2][r][t] + part[3][r][t] + bj;
        g_xproj[(size_t)(m0 + r) * 256 + t] = v;
    }
}

// ---------------------------------------------------------------------------
// Kernel 2: the scan. 64 CTAs, one batch row each (independent recurrences).
// 512 threads: ks = t>>6 (8-way k-split, 32 k's), jq = t&63 (4 columns).
// W_hh resident: per thread, k-range first 20 k's in REGISTERS (40 f32x2 =
// 80 regs), last 12 k's in SMEM (96 KB). Zero gmem W traffic in steady state.
// h kept in SMEM pre-replicated as (h,h) f32x2 pairs -> no packing in loop.
// Math via fma.rn.f32x2 (FFMA2): 2 FMAs/instr.
// ---------------------------------------------------------------------------
#define K_REG  20
#define K_SMEM 12

__global__ __launch_bounds__(512, 1) void scan_kernel(
    const float* __restrict__ Whh,    // [256,256] row-major (k, j)
    const float* __restrict__ h0,     // [64,256]
    float* __restrict__ out)          // [64,256]
{
    extern __shared__ ull smem[];
    // layout: sW [8][12][64] ulonglong2  (96 KB)
    //         part [8][128] ull          (8 KB)
    //         hbuf [256] ull             (2 KB)
    ulonglong2* sW   = (ulonglong2*)smem;                       // 8*12*64 entries
    ull*        part = (ull*)(smem + 8 * 12 * 64 * 2);          // 8*128
    ull*        hbuf = part + 8 * 128;                          // 256

    const int t  = threadIdx.x;
    const int b  = blockIdx.x;
    const int ks = t >> 6;        // 0..7
    const int jq = t & 63;        // 4 columns: 4jq .. 4jq+3
    const int kbase = ks * 32;

    // ---- one-time: load register-resident W slice (20 k's x 4 cols) ----
    ull wr[2 * K_REG];
    #pragma unroll
    for (int i = 0; i < K_REG; i++) {
        const int k = kbase + i;
        const ulonglong2 wv = *(const ulonglong2*)&Whh[k * 256 + 4 * jq];
        wr[2 * i]     = wv.x;   // cols (4jq, 4jq+1)
        wr[2 * i + 1] = wv.y;   // cols (4jq+2, 4jq+3)
    }

    // ---- one-time: fill SMEM W slice (12 k's per ks-group) ----
    for (int idx = t; idx < 8 * K_SMEM * 64; idx += 512) {
        const int fjq = idx & 63;
        const int fm  = (idx >> 6) % K_SMEM;
        const int fks = idx / (K_SMEM * 64);
        const int k   = fks * 32 + K_REG + fm;
        sW[(fks * K_SMEM + fm) * 64 + fjq] =
            *(const ulonglong2*)&Whh[k * 256 + 4 * fjq];
    }

    // ---- init h (replicated pairs) ----
    if (t < 256) {
        const float h = h0[(size_t)b * 256 + t];
        hbuf[t] = pack2(h, h);
    }
    __syncthreads();

    // x_proj prefetch state (threads t<128 own column-pair t)
    ull xcur = 0, xnext = 0;
    if (t < 128) {
        xcur = *(const ull*)&g_xproj[((size_t)0 * B_SZ + b) * 256 + 2 * t];
    }

    const ull* hb = hbuf + kbase;

    for (int s = 0; s < S_LEN; s++) {
        // prefetch next step's x (lands during this step's FMA phase)
        if (t < 128) {
            const int sn = (s + 1 < S_LEN) ? s + 1 : s;
            xnext = *(const ull*)&g_xproj[((size_t)sn * B_SZ + b) * 256 + 2 * t];
        }

        ull a01 = 0, a23 = 0;   // packed (0.0f,0.0f)

        // register half: k = kbase + 0 .. kbase + 19
        #pragma unroll
        for (int p = 0; p < K_REG / 2; p++) {
            const ulonglong2 hv = *(const ulonglong2*)(hb + 2 * p);
            a01 = fma2(wr[4 * p + 0], hv.x, a01);
            a23 = fma2(wr[4 * p + 1], hv.x, a23);
            a01 = fma2(wr[4 * p + 2], hv.y, a01);
            a23 = fma2(wr[4 * p + 3], hv.y, a23);
        }
        // smem half: k = kbase + 20 .. kbase + 31
        #pragma unroll
        for (int m = 0; m < K_SMEM; m += 2) {
            const ulonglong2 hv = *(const ulonglong2*)(hb + K_REG + m);
            const ulonglong2 w0 = sW[(ks * K_SMEM + m) * 64 + jq];
            const ulonglong2 w1 = sW[(ks * K_SMEM + m + 1) * 64 + jq];
            a01 = fma2(w0.x, hv.x, a01);
            a23 = fma2(w0.y, hv.x, a23);
            a01 = fma2(w1.x, hv.y, a01);
            a23 = fma2(w1.y, hv.y, a23);
        }

        // partials: col-pair index cp = 2*jq (+0/+1)
        part[ks * 128 + 2 * jq]     = a01;
        part[ks * 128 + 2 * jq + 1] = a23;
        __syncthreads();

        // reduce 8 k-groups, add x, tanh, write replicated h
        if (t < 128) {
            ull v = add2(add2(part[0 * 128 + t], part[1 * 128 + t]),
                         add2(part[2 * 128 + t], part[3 * 128 + t]));
            ull w = add2(add2(part[4 * 128 + t], part[5 * 128 + t]),
                         add2(part[6 * 128 + t], part[7 * 128 + t]));
            v = add2(add2(v, w), xcur);
            float vx, vy;
            unpack2(v, vx, vy);
            const float tx = tanhf(vx);
            const float ty = tanhf(vy);
            hbuf[2 * t]     = pack2(tx, tx);
            hbuf[2 * t + 1] = pack2(ty, ty);
            xcur = xnext;
        }
        __syncthreads();
    }

    if (t < 128) {
        float vx, vy;
        unpack2(hbuf[2 * t], vx, vy);   // both halves equal
        float wx, wy;
        unpack2(hbuf[2 * t + 1], wx, wy);
        out[(size_t)b * 256 + 2 * t]     = vx;
        out[(size_t)b * 256 + 2 * t + 1] = wx;
    }
}

// ---------------------------------------------------------------------------
extern "C" void kernel_launch(void* const* d_in, const int* in_sizes, int n_in,
                              void* d_out, int out_size)
{
    const float* sentence = (const float*)d_in[0];
    const float* h0       = (const float*)d_in[1];
    const float* W_ih     = (const float*)d_in[2];
    const float* W_hh     = (const float*)d_in[3];
    const float* bias     = (const float*)d_in[4];
    float* out = (float*)d_out;

    (void)in_sizes; (void)n_in; (void)out_size;

    xproj_kernel<<<(S_LEN * B_SZ) / 8, 256>>>(sentence, W_ih, bias);

    const int smem_bytes = (8 * K_SMEM * 64) * 16 + (8 * 128) * 8 + 256 * 8;
    static bool attr_set = false;
    if (!attr_set) {
        cudaFuncSetAttribute(scan_kernel,
                             cudaFuncAttributeMaxDynamicSharedMemorySize,
                             smem_bytes);
        attr_set = true;
    }
    scan_kernel<<<B_SZ, 512, smem_bytes>>>(W_hh, h0, out);
}

// round 4
// speedup vs baseline: 5.0554x; 1.0001x over previous
#include <cuda_runtime.h>
#include <math.h>

#define S_LEN 2048
#define B_SZ  64
#define E_SZ  256
#define H_SZ  256

// Scratch for x_proj: [S, B, H] fp32 = 134 MB
__device__ float g_xproj[(size_t)S_LEN * B_SZ * H_SZ];

typedef unsigned long long ull;

// ---- packed f32x2 helpers (Blackwell sm_103a) -------------------------------
__device__ __forceinline__ ull fma2(ull a, ull b, ull c) {
    ull d;
    asm("fma.rn.f32x2 %0, %1, %2, %3;" : "=l"(d) : "l"(a), "l"(b), "l"(c));
    return d;
}
__device__ __forceinline__ ull add2(ull a, ull b) {
    ull d;
    asm("add.rn.f32x2 %0, %1, %2;" : "=l"(d) : "l"(a), "l"(b));
    return d;
}
__device__ __forceinline__ ull pack2(float lo, float hi) {
    ull d;
    asm("mov.b64 %0, {%1, %2};" : "=l"(d) : "f"(lo), "f"(hi));
    return d;
}
__device__ __forceinline__ void unpack2(ull v, float& lo, float& hi) {
    asm("mov.b64 {%0, %1}, %2;" : "=f"(lo), "=f"(hi) : "l"(v));
}

// ---------------------------------------------------------------------------
// Kernel 1: x_proj = sentence @ W_ih + b   (unchanged from R1 — works, ~0.4ms)
// ---------------------------------------------------------------------------
__global__ __launch_bounds__(256) void xproj_kernel(
    const float* __restrict__ sent,
    const float* __restrict__ Wih,
    const float* __restrict__ bias)
{
    __shared__ float xs[8][256];
    __shared__ float part[4][8][256];

    const int t  = threadIdx.x;
    const int m0 = blockIdx.x * 8;

    {
        const float4* srow = (const float4*)(sent + (size_t)m0 * 256);
        float4* xs4 = (float4*)&xs[0][0];
        #pragma unroll
        for (int i = 0; i < 2; i++)
            xs4[t + i * 256] = srow[t + i * 256];
    }
    __syncthreads();

    const int jg = t & 63;
    const int ks = t >> 6;
    const float4* W4 = (const float4*)Wih;

    float4 acc[8];
    #pragma unroll
    for (int r = 0; r < 8; r++) acc[r] = make_float4(0.f, 0.f, 0.f, 0.f);

    #pragma unroll 8
    for (int i = 0; i < 64; i++) {
        const int k = ks * 64 + i;
        const float4 w = W4[k * 64 + jg];
        #pragma unroll
        for (int r = 0; r < 8; r++) {
            const float xv = xs[r][k];
            acc[r].x += xv * w.x;
            acc[r].y += xv * w.y;
            acc[r].z += xv * w.z;
            acc[r].w += xv * w.w;
        }
    }

    #pragma unroll
    for (int r = 0; r < 8; r++)
        *(float4*)&part[ks][r][4 * jg] = acc[r];
    __syncthreads();

    const float bj = bias[t];
    #pragma unroll
    for (int r = 0; r < 8; r++) {
        const float v = part[0][r][t] + part[1][r][t] +
                        part[2][r][t] + part[3][r][t] + bj;
        g_xproj[(size_t)(m0 + r) * 256 + t] = v;
    }
}

// ---------------------------------------------------------------------------
// Kernel 2: the scan. 64 CTAs, one batch row each (independent recurrences).
// 512 threads: ks = t>>6 (8-way k-split, 32 k's), jq = t&63 (4 columns).
// W_hh resident: per thread, k-range first 20 k's in REGISTERS (40 f32x2 =
// 80 regs), last 12 k's in SMEM (96 KB). Zero gmem W traffic in steady state.
// h kept in SMEM pre-replicated as (h,h) f32x2 pairs -> no packing in loop.
// Math via fma.rn.f32x2 (FFMA2): 2 FMAs/instr.
// ---------------------------------------------------------------------------
#define K_REG  20
#define K_SMEM 12

__global__ __launch_bounds__(512, 1) void scan_kernel(
    const float* __restrict__ Whh,    // [256,256] row-major (k, j)
    const float* __restrict__ h0,     // [64,256]
    float* __restrict__ out)          // [64,256]
{
    extern __shared__ ull smem[];
    // layout: sW [8][12][64] ulonglong2  (96 KB)
    //         part [8][128] ull          (8 KB)
    //         hbuf [256] ull             (2 KB)
    ulonglong2* sW   = (ulonglong2*)smem;                       // 8*12*64 entries
    ull*        part = (ull*)(smem + 8 * 12 * 64 * 2);          // 8*128
    ull*        hbuf = part + 8 * 128;                          // 256

    const int t  = threadIdx.x;
    const int b  = blockIdx.x;
    const int ks = t >> 6;        // 0..7
    const int jq = t & 63;        // 4 columns: 4jq .. 4jq+3
    const int kbase = ks * 32;

    // ---- one-time: load register-resident W slice (20 k's x 4 cols) ----
    ull wr[2 * K_REG];
    #pragma unroll
    for (int i = 0; i < K_REG; i++) {
        const int k = kbase + i;
        const ulonglong2 wv = *(const ulonglong2*)&Whh[k * 256 + 4 * jq];
        wr[2 * i]     = wv.x;   // cols (4jq, 4jq+1)
        wr[2 * i + 1] = wv.y;   // cols (4jq+2, 4jq+3)
    }

    // ---- one-time: fill SMEM W slice (12 k's per ks-group) ----
    for (int idx = t; idx < 8 * K_SMEM * 64; idx += 512) {
        const int fjq = idx & 63;
        const int fm  = (idx >> 6) % K_SMEM;
        const int fks = idx / (K_SMEM * 64);
        const int k   = fks * 32 + K_REG + fm;
        sW[(fks * K_SMEM + fm) * 64 + fjq] =
            *(const ulonglong2*)&Whh[k * 256 + 4 * fjq];
    }

    // ---- init h (replicated pairs) ----
    if (t < 256) {
        const float h = h0[(size_t)b * 256 + t];
        hbuf[t] = pack2(h, h);
    }
    __syncthreads();

    // x_proj prefetch state (threads t<128 own column-pair t)
    ull xcur = 0, xnext = 0;
    if (t < 128) {
        xcur = *(const ull*)&g_xproj[((size_t)0 * B_SZ + b) * 256 + 2 * t];
    }

    const ull* hb = hbuf + kbase;

    for (int s = 0; s < S_LEN; s++) {
        // prefetch next step's x (lands during this step's FMA phase)
        if (t < 128) {
            const int sn = (s + 1 < S_LEN) ? s + 1 : s;
            xnext = *(const ull*)&g_xproj[((size_t)sn * B_SZ + b) * 256 + 2 * t];
        }

        ull a01 = 0, a23 = 0;   // packed (0.0f,0.0f)

        // register half: k = kbase + 0 .. kbase + 19
        #pragma unroll
        for (int p = 0; p < K_REG / 2; p++) {
            const ulonglong2 hv = *(const ulonglong2*)(hb + 2 * p);
            a01 = fma2(wr[4 * p + 0], hv.x, a01);
            a23 = fma2(wr[4 * p + 1], hv.x, a23);
            a01 = fma2(wr[4 * p + 2], hv.y, a01);
            a23 = fma2(wr[4 * p + 3], hv.y, a23);
        }
        // smem half: k = kbase + 20 .. kbase + 31
        #pragma unroll
        for (int m = 0; m < K_SMEM; m += 2) {
            const ulonglong2 hv = *(const ulonglong2*)(hb + K_REG + m);
            const ulonglong2 w0 = sW[(ks * K_SMEM + m) * 64 + jq];
            const ulonglong2 w1 = sW[(ks * K_SMEM + m + 1) * 64 + jq];
            a01 = fma2(w0.x, hv.x, a01);
            a23 = fma2(w0.y, hv.x, a23);
            a01 = fma2(w1.x, hv.y, a01);
            a23 = fma2(w1.y, hv.y, a23);
        }

        // partials: col-pair index cp = 2*jq (+0/+1)
        part[ks * 128 + 2 * jq]     = a01;
        part[ks * 128 + 2 * jq + 1] = a23;
        __syncthreads();

        // reduce 8 k-groups, add x, tanh, write replicated h
        if (t < 128) {
            ull v = add2(add2(part[0 * 128 + t], part[1 * 128 + t]),
                         add2(part[2 * 128 + t], part[3 * 128 + t]));
            ull w = add2(add2(part[4 * 128 + t], part[5 * 128 + t]),
                         add2(part[6 * 128 + t], part[7 * 128 + t]));
            v = add2(add2(v, w), xcur);
            float vx, vy;
            unpack2(v, vx, vy);
            const float tx = tanhf(vx);
            const float ty = tanhf(vy);
            hbuf[2 * t]     = pack2(tx, tx);
            hbuf[2 * t + 1] = pack2(ty, ty);
            xcur = xnext;
        }
        __syncthreads();
    }

    if (t < 128) {
        float vx, vy;
        unpack2(hbuf[2 * t], vx, vy);   // both halves equal
        float wx, wy;
        unpack2(hbuf[2 * t + 1], wx, wy);
        out[(size_t)b * 256 + 2 * t]     = vx;
        out[(size_t)b * 256 + 2 * t + 1] = wx;
    }
}

// ---------------------------------------------------------------------------
extern "C" void kernel_launch(void* const* d_in, const int* in_sizes, int n_in,
                              void* d_out, int out_size)
{
    const float* sentence = (const float*)d_in[0];
    const float* h0       = (const float*)d_in[1];
    const float* W_ih     = (const float*)d_in[2];
    const float* W_hh     = (const float*)d_in[3];
    const float* bias     = (const float*)d_in[4];
    float* out = (float*)d_out;

    (void)in_sizes; (void)n_in; (void)out_size;

    xproj_kernel<<<(S_LEN * B_SZ) / 8, 256>>>(sentence, W_ih, bias);

    const int smem_bytes = (8 * K_SMEM * 64) * 16 + (8 * 128) * 8 + 256 * 8;
    static bool attr_set = false;
    if (!attr_set) {
        cudaFuncSetAttribute(scan_kernel,
                             cudaFuncAttributeMaxDynamicSharedMemorySize,
                             smem_bytes);
        attr_set = true;
    }
    scan_kernel<<<B_SZ, 512, smem_bytes>>>(W_hh, h0, out);
}